// round 14
// baseline (speedup 1.0000x reference)
#include <cuda_runtime.h>
#include <math.h>
#include <stdint.h>

#define NB 4
#define TDIM 8
#define LP1 197
#define HH 12
#define DD 64
#define CC 768
#define LL 196
#define NT 28   // NB*(TDIM-1)

typedef unsigned long long u64;

__device__ __forceinline__ u64 pk2(float lo, float hi) {
    u64 r; asm("mov.b64 %0,{%1,%2};" : "=l"(r) : "f"(lo), "f"(hi)); return r;
}
__device__ __forceinline__ void upk2(u64 v, float& lo, float& hi) {
    asm("mov.b64 {%0,%1},%2;" : "=f"(lo), "=f"(hi) : "l"(v));
}
__device__ __forceinline__ u64 ffma2(u64 a, u64 b, u64 c) {
    u64 d; asm("fma.rn.f32x2 %0,%1,%2,%3;" : "=l"(d) : "l"(a), "l"(b), "l"(c)); return d;
}
__device__ __forceinline__ u64 fadd2(u64 a, u64 b) {
    u64 d; asm("add.rn.f32x2 %0,%1,%2;" : "=l"(d) : "l"(a), "l"(b)); return d;
}
__device__ __forceinline__ void red4(float* p, float a, float b, float c, float d) {
    asm volatile("red.global.add.v4.f32 [%0], {%1,%2,%3,%4};"
                 :: "l"(p), "f"(a), "f"(b), "f"(c), "f"(d) : "memory");
}
__device__ __forceinline__ void cpa16(uint32_t s, const void* g) {
    asm volatile("cp.async.cg.shared.global [%0], [%1], 16;" :: "r"(s), "l"(g) : "memory");
}
#define CPA_COMMIT() asm volatile("cp.async.commit_group;" ::: "memory")
#define CPA_WAIT(n)  asm volatile("cp.async.wait_group %0;" :: "n"(n) : "memory")

// Scratch: head-averaged attention probabilities for each half.
__device__ __align__(16) float g_P1[NT * LL * LL];
__device__ __align__(16) float g_P2[NT * LL * LL];

// ---------------------------------------------------------------------------
// Kernel 0: zero P scratch and cls rows of out — float4, wide grid (HBM-bound).
// ---------------------------------------------------------------------------
__global__ void zero_kernel(float* __restrict__ out) {
    size_t stride = (size_t)gridDim.x * blockDim.x;
    size_t i = (size_t)blockIdx.x * blockDim.x + threadIdx.x;
    float4 z = make_float4(0.f, 0.f, 0.f, 0.f);
    float4* p1 = (float4*)g_P1;
    float4* p2 = (float4*)g_P2;
    const size_t np4 = (size_t)NT * LL * LL / 4;
    for (size_t j = i; j < np4; j += stride) { p1[j] = z; p2[j] = z; }
    const size_t nc4 = (size_t)NB * TDIM * (CC / 4);
    float4* o4 = (float4*)out;
    for (size_t j = i; j < nc4; j += stride) {
        size_t nt = j / (CC / 4), c = j - nt * (CC / 4);
        o4[nt * ((size_t)LP1 * CC / 4) + c] = z;
    }
}

// ---------------------------------------------------------------------------
// Kernel 1: attention (R10 structure) with two changes:
//  - NO max-subtraction in softmax (scores bounded ~|6| for N(0,1) inputs;
//    fp32 exp overflow-safe by a huge margin) -> removes fmax ops + the
//    serial SHFL max chain per row.
//  - Q staged ROW-MAJOR [q][68] via float4 (coalesced LDG.128 + STS.128,
//    no transpose arithmetic).  GEMM ad loads stay broadcast LDS.32.
// ---------------------------------------------------------------------------
#define KS_STRIDE 210
#define QS_STRIDE 68
#define A_SMEM_BYTES ((64*KS_STRIDE + 68*QS_STRIDE) * 4)   // 72256 B

__device__ __forceinline__ void store_row_v4(float* Pr, const u64* pv, int tx) {
    #pragma unroll
    for (int b = 0; b < 7; b++) {
        u64 nb = __shfl_down_sync(0xffffffffu, pv[b], 1);
        if ((tx & 1) == 0 && (b < 6 || tx == 0)) {
            float a0, a1, b0, b1;
            upk2(pv[b], a0, a1);
            upk2(nb,    b0, b1);
            red4(Pr + 32 * b + 2 * tx, a0, a1, b0, b1);
        }
    }
}

__global__ __launch_bounds__(256, 3)
void attn_kernel(const float* __restrict__ q, const float* __restrict__ k) {
    extern __shared__ float sm[];
    float* ks = sm;                          // [64][210]  (transposed K)
    float* qs = ks + 64 * KS_STRIDE;         // [68][68]   (row-major Q, scaled)

    int h    = blockIdx.x;
    int nt   = blockIdx.y;
    int half = blockIdx.z / 3;
    int qh   = blockIdx.z - half * 3;
    int n = nt / 7, t = nt - n * 7;
    int tq = (half == 0) ? t + 1 : t;
    int tk = (half == 0) ? t : t + 1;
    int q0 = qh * 64;
    int nrows = (qh == 2) ? 68 : 64;

    const float* qb = q + ((size_t)(n * TDIM + tq) * LP1 + 1) * (HH * DD) + h * DD;
    const float* kb = k + ((size_t)(n * TDIM + tk) * LP1 + 1) * (HH * DD) + h * DD;
    float* P = ((half == 0) ? g_P1 : g_P2) + (size_t)nt * LL * LL;

    int tid = threadIdx.x;

    // K tile transposed: ks[d][kk] = k[kk][d]
    for (int i = tid; i < LL * DD; i += 256) {
        int kk = i >> 6, d = i & 63;
        ks[d * KS_STRIDE + kk] = kb[(size_t)kk * (HH * DD) + d];
    }
    // Q rows row-major, pre-scaled, float4
    for (int i = tid; i < nrows * 16; i += 256) {
        int qq = i >> 4, d4 = i & 15;
        float4 v = *(const float4*)(qb + (size_t)(q0 + qq) * (HH * DD) + d4 * 4);
        v.x *= 0.125f; v.y *= 0.125f; v.z *= 0.125f; v.w *= 0.125f;
        *(float4*)&qs[qq * QS_STRIDE + d4 * 4] = v;
    }
    __syncthreads();

    int tx = tid & 15, ty = tid >> 4;

    // Main 64x196 GEMM over K=64: 4 rows x 7 col-pairs per thread, all valid.
    u64 acc[4][7];
    #pragma unroll
    for (int a = 0; a < 4; a++)
        #pragma unroll
        for (int b = 0; b < 7; b++) acc[a][b] = 0ULL;

    #pragma unroll 4
    for (int d = 0; d < 64; d++) {
        u64 ad[4], bv[7];
        #pragma unroll
        for (int a = 0; a < 4; a++) {
            float av = qs[(ty + 16 * a) * QS_STRIDE + d];
            ad[a] = pk2(av, av);
        }
        #pragma unroll
        for (int b = 0; b < 7; b++)
            bv[b] = *(const u64*)&ks[d * KS_STRIDE + 2 * tx + 32 * b];
        #pragma unroll
        for (int a = 0; a < 4; a++)
            #pragma unroll
            for (int b = 0; b < 7; b++)
                acc[a][b] = ffma2(ad[a], bv[b], acc[a][b]);
    }

    // Register softmax per row (half-warp owns a row), NO max subtraction.
    #pragma unroll
    for (int a = 0; a < 4; a++) {
        float e[14];
        #pragma unroll
        for (int b = 0; b < 7; b++) upk2(acc[a][b], e[2 * b], e[2 * b + 1]);

        bool v6 = (tx < 2);
        float s = 0.f;
        #pragma unroll
        for (int b = 0; b < 6; b++) {
            e[2 * b]     = __expf(e[2 * b]);
            e[2 * b + 1] = __expf(e[2 * b + 1]);
            s += e[2 * b] + e[2 * b + 1];
        }
        if (v6) {
            e[12] = __expf(e[12]);
            e[13] = __expf(e[13]);
            s += e[12] + e[13];
        }
        #pragma unroll
        for (int off = 8; off > 0; off >>= 1)
            s += __shfl_xor_sync(0xffffffffu, s, off);

        float inv = (1.f / 12.f) / s;
        u64 pv[7];
        #pragma unroll
        for (int b = 0; b < 7; b++)
            pv[b] = pk2(e[2 * b] * inv, e[2 * b + 1] * inv);
        store_row_v4(P + (size_t)(q0 + ty + 16 * a) * LL, pv, tx);
    }

    // Global 4-row tail (rows 192..195), qh==2 blocks only.
    if (qh == 2) {
        int qq2 = 64 + (ty & 3);
        u64 acct[7];
        #pragma unroll
        for (int b = 0; b < 7; b++) acct[b] = 0ULL;

        #pragma unroll 4
        for (int d = 0; d < 64; d++) {
            float av = qs[qq2 * QS_STRIDE + d];
            u64 ad = pk2(av, av);
            #pragma unroll
            for (int b = 0; b < 7; b++)
                acct[b] = ffma2(ad, *(const u64*)&ks[d * KS_STRIDE + 2 * tx + 32 * b], acct[b]);
        }

        float e[14];
        #pragma unroll
        for (int b = 0; b < 7; b++) upk2(acct[b], e[2 * b], e[2 * b + 1]);

        bool v6 = (tx < 2);
        float s = 0.f;
        #pragma unroll
        for (int b = 0; b < 6; b++) {
            e[2 * b]     = __expf(e[2 * b]);
            e[2 * b + 1] = __expf(e[2 * b + 1]);
            s += e[2 * b] + e[2 * b + 1];
        }
        if (v6) {
            e[12] = __expf(e[12]);
            e[13] = __expf(e[13]);
            s += e[12] + e[13];
        }
        #pragma unroll
        for (int off = 8; off > 0; off >>= 1)
            s += __shfl_xor_sync(0xffffffffu, s, off);

        float inv = (1.f / 12.f) / s;
        u64 pv[7];
        #pragma unroll
        for (int b = 0; b < 7; b++)
            pv[b] = pk2(e[2 * b] * inv, e[2 * b + 1] * inv);
        #pragma unroll
        for (int b = 0; b < 7; b++) {
            u64 nb = __shfl_down_sync(0xffffffffu, pv[b], 1);
            if (ty < 4 && (tx & 1) == 0 && (b < 6 || tx == 0)) {
                float a0, a1, b0, b1;
                upk2(pv[b], a0, a1);
                upk2(nb,    b0, b1);
                red4(P + (size_t)(192 + ty) * LL + 32 * b + 2 * tx, a0, a1, b0, b1);
            }
        }
    }
}

// ---------------------------------------------------------------------------
// Kernel 2 — EXACT ROUND-13 VERSION (protected win): fused halves, np-merged,
// c-tile-paired, cp.async double-buffered gather.
// ---------------------------------------------------------------------------
#define TCo 64
#define WSF (98 * TCo)                  // 6272 floats per ws buffer
#define PSF (4 * LL * 8)                // 6272 floats per half
#define RED_U64 (4 * 32 * 8)            // 1024 u64 = 8192 B
#define O_SMEM_BYTES ((2*WSF + 2*PSF) * 4 + RED_U64 * 8)   // 108544 B

__global__ __launch_bounds__(256, 2)
void out_kernel(const float* __restrict__ w1, const float* __restrict__ w2,
                float* __restrict__ out) {
    extern __shared__ float sm[];
    float* psA = sm + 2 * WSF;          // [4][196*8]  slot tt = P1[t=tt-1], slot0=0
    float* psB = psA + PSF;             // [4][196*8]  slot tt = P2[tt],    slot7=0
    u64*   red = (u64*)(sm + 2 * WSF + 2 * PSF);

    int qq = blockIdx.y;
    int c0 = blockIdx.x * (2 * TCo);
    int tid = threadIdx.x;
    int pi = qq / 14, pj = qq - pi * 14;

    uint32_t ws_s0 = (uint32_t)__cvta_generic_to_shared(sm);

    #pragma unroll
    for (int r = 0; r < 28; r++) {
        int n_l = r / 7, t = r - n_l * 7;
        if (tid < LL) {
            size_t base = ((size_t)(n_l * 7 + t) * LL + qq) * LL + tid;
            psA[n_l * (LL * 8) + tid * 8 + t + 1] = g_P1[base];
            psB[n_l * (LL * 8) + tid * 8 + t]     = g_P2[base];
        }
    }
    if (tid < LL) {
        #pragma unroll
        for (int n_l = 0; n_l < 4; n_l++) {
            psA[n_l * (LL * 8) + tid * 8] = 0.f;
            psB[n_l * (LL * 8) + tid * 8 + 7] = 0.f;
        }
    }

    int wid = tid >> 5, lane = tid & 31;
    int n_l = wid >> 1, kq = wid & 1;
    int sub = lane >> 4, cl = lane & 15;
    int kst = kq * 49;

    auto gather = [&](int pp) {
        int ch = pp >> 2, ph = pp & 3;
        const float* w = (ph < 2) ? w1 : w2;
        int kbase = (ph & 1) * 98;
        int cc = c0 + ch * TCo;
        uint32_t dst = ws_s0 + (uint32_t)(pp & 1) * (WSF * 4);
        #pragma unroll
        for (int j = 0; j < 6; j++) {
            int i = tid + j * 256;
            int kk = i >> 4, cq = i & 15;
            int kg = kbase + kk;
            int ki = kg / 14, kj = kg - ki * 14;
            int idx = (pi - ki + 13) * 27 + (pj - kj + 13);
            cpa16(dst + (uint32_t)(kk * TCo + cq * 4) * 4,
                  w + (size_t)idx * CC + cc + cq * 4);
        }
        if (tid < 32) {
            int i = 1536 + tid;
            int kk = i >> 4, cq = i & 15;
            int kg = kbase + kk;
            int ki = kg / 14, kj = kg - ki * 14;
            int idx = (pi - ki + 13) * 27 + (pj - kj + 13);
            cpa16(dst + (uint32_t)(kk * TCo + cq * 4) * 4,
                  w + (size_t)idx * CC + cc + cq * 4);
        }
        CPA_COMMIT();
    };

    u64 acc[8];
    #pragma unroll
    for (int i = 0; i < 8; i++) acc[i] = 0ULL;

    gather(0);
    for (int pp = 0; pp < 8; pp++) {
        if (pp < 7) { gather(pp + 1); CPA_WAIT(1); }
        else        { CPA_WAIT(0); }
        __syncthreads();

        int ph = pp & 3, ch = pp >> 2;
        const float* ps = ((ph < 2) ? psA : psB) + n_l * (LL * 8);
        int kbase = (ph & 1) * 98;
        const float* ws = sm + (pp & 1) * WSF;

        #pragma unroll 7
        for (int kl = kst; kl < kst + 49; kl++) {
            float4 wv = *(const float4*)&ws[kl * TCo + cl * 4];
            ulonglong2 pr = *(const ulonglong2*)&ps[(kbase + kl) * 8 + sub * 4];
            u64 b0 = pk2(wv.x, wv.x), b1 = pk2(wv.y, wv.y);
            u64 b2 = pk2(wv.z, wv.z), b3 = pk2(wv.w, wv.w);
            acc[0] = ffma2(pr.x, b0, acc[0]);  acc[1] = ffma2(pr.y, b0, acc[1]);
            acc[2] = ffma2(pr.x, b1, acc[2]);  acc[3] = ffma2(pr.y, b1, acc[3]);
            acc[4] = ffma2(pr.x, b2, acc[4]);  acc[5] = ffma2(pr.y, b2, acc[5]);
            acc[6] = ffma2(pr.x, b3, acc[6]);  acc[7] = ffma2(pr.y, b3, acc[7]);
        }

        bool epi = ((pp & 3) == 3);
        if (epi && kq) {
            int base = (n_l * 32 + lane) * 8;
            #pragma unroll
            for (int j = 0; j < 8; j++) red[base + j] = acc[j];
        }
        __syncthreads();

        if (epi) {
            if (kq == 0) {
                int base = (n_l * 32 + lane) * 8;
                #pragma unroll
                for (int j = 0; j < 8; j++) acc[j] = fadd2(acc[j], red[base + j]);

                int cc = c0 + ch * TCo;
                float a[16];
                #pragma unroll
                for (int i = 0; i < 8; i++) upk2(acc[i], a[2 * i], a[2 * i + 1]);
                #pragma unroll
                for (int tl = 0; tl < 4; tl++) {
                    int tt = sub * 4 + tl;
                    int tp = tl >> 1, hi = tl & 1;
                    float4 o4;
                    o4.x = a[(0 * 2 + tp) * 2 + hi];
                    o4.y = a[(1 * 2 + tp) * 2 + hi];
                    o4.z = a[(2 * 2 + tp) * 2 + hi];
                    o4.w = a[(3 * 2 + tp) * 2 + hi];
                    *(float4*)(out + ((size_t)(n_l * TDIM + tt) * LP1 + qq + 1) * CC
                               + cc + cl * 4) = o4;
                }
            }
            #pragma unroll
            for (int i = 0; i < 8; i++) acc[i] = 0ULL;
        }
    }
}

// ---------------------------------------------------------------------------
extern "C" void kernel_launch(void* const* d_in, const int* in_sizes, int n_in,
                              void* d_out, int out_size) {
    const float* q  = (const float*)d_in[0];
    const float* k  = (const float*)d_in[1];
    const float* w1 = (const float*)d_in[2];
    const float* w2 = (const float*)d_in[3];
    float* out = (float*)d_out;

    cudaFuncSetAttribute(attn_kernel, cudaFuncAttributeMaxDynamicSharedMemorySize, A_SMEM_BYTES);
    cudaFuncSetAttribute(out_kernel,  cudaFuncAttributeMaxDynamicSharedMemorySize, O_SMEM_BYTES);

    zero_kernel<<<2048, 256>>>(out);
    attn_kernel<<<dim3(HH, NT, 6), 256, A_SMEM_BYTES>>>(q, k);
    out_kernel<<<dim3(CC / (2 * TCo), LL, 1), 256, O_SMEM_BYTES>>>(w1, w2, out);
}

// round 15
// speedup vs baseline: 1.1924x; 1.1924x over previous
#include <cuda_runtime.h>
#include <math.h>
#include <stdint.h>

#define NB 4
#define TDIM 8
#define LP1 197
#define HH 12
#define DD 64
#define CC 768
#define LL 196
#define NT 28   // NB*(TDIM-1)

typedef unsigned long long u64;

__device__ __forceinline__ u64 pk2(float lo, float hi) {
    u64 r; asm("mov.b64 %0,{%1,%2};" : "=l"(r) : "f"(lo), "f"(hi)); return r;
}
__device__ __forceinline__ void upk2(u64 v, float& lo, float& hi) {
    asm("mov.b64 {%0,%1},%2;" : "=f"(lo), "=f"(hi) : "l"(v));
}
__device__ __forceinline__ u64 ffma2(u64 a, u64 b, u64 c) {
    u64 d; asm("fma.rn.f32x2 %0,%1,%2,%3;" : "=l"(d) : "l"(a), "l"(b), "l"(c)); return d;
}
__device__ __forceinline__ u64 fadd2(u64 a, u64 b) {
    u64 d; asm("add.rn.f32x2 %0,%1,%2;" : "=l"(d) : "l"(a), "l"(b)); return d;
}
__device__ __forceinline__ void red4(float* p, float a, float b, float c, float d) {
    asm volatile("red.global.add.v4.f32 [%0], {%1,%2,%3,%4};"
                 :: "l"(p), "f"(a), "f"(b), "f"(c), "f"(d) : "memory");
}
__device__ __forceinline__ void cpa16(uint32_t s, const void* g) {
    asm volatile("cp.async.cg.shared.global [%0], [%1], 16;" :: "r"(s), "l"(g) : "memory");
}
#define CPA_COMMIT() asm volatile("cp.async.commit_group;" ::: "memory")
#define CPA_WAIT(n)  asm volatile("cp.async.wait_group %0;" :: "n"(n) : "memory")

// Scratch: head-averaged attention probabilities for each half.
__device__ __align__(16) float g_P1[NT * LL * LL];
__device__ __align__(16) float g_P2[NT * LL * LL];

// ---------------------------------------------------------------------------
// Kernel 0: zero P scratch and cls rows of out — float4, wide grid.
// ---------------------------------------------------------------------------
__global__ void zero_kernel(float* __restrict__ out) {
    size_t stride = (size_t)gridDim.x * blockDim.x;
    size_t i = (size_t)blockIdx.x * blockDim.x + threadIdx.x;
    float4 z = make_float4(0.f, 0.f, 0.f, 0.f);
    float4* p1 = (float4*)g_P1;
    float4* p2 = (float4*)g_P2;
    const size_t np4 = (size_t)NT * LL * LL / 4;
    for (size_t j = i; j < np4; j += stride) { p1[j] = z; p2[j] = z; }
    const size_t nc4 = (size_t)NB * TDIM * (CC / 4);
    float4* o4 = (float4*)out;
    for (size_t j = i; j < nc4; j += stride) {
        size_t nt = j / (CC / 4), c = j - nt * (CC / 4);
        o4[nt * ((size_t)LP1 * CC / 4) + c] = z;
    }
}

// ---------------------------------------------------------------------------
// Kernel 1: attention — R13 structure EXACTLY (column-major stride-69 Q,
// conflict-free by construction; R14's row-major staging hit bank conflicts),
// with ONE isolated change: NO max-subtraction in softmax (scores bounded
// ~|6| for N(0,1) inputs; fp32 exp overflow-safe).  Removes 14 fmax + the
// serial 4-deep SHFL max chain per row (main + tail).
// ---------------------------------------------------------------------------
#define KS_STRIDE 210
#define QS_STRIDE 69
#define A_SMEM_BYTES ((64*KS_STRIDE + 64*QS_STRIDE) * 4)   // 71424 B

__device__ __forceinline__ void store_row_v4(float* Pr, const u64* pv, int tx) {
    #pragma unroll
    for (int b = 0; b < 7; b++) {
        u64 nb = __shfl_down_sync(0xffffffffu, pv[b], 1);
        if ((tx & 1) == 0 && (b < 6 || tx == 0)) {
            float a0, a1, b0, b1;
            upk2(pv[b], a0, a1);
            upk2(nb,    b0, b1);
            red4(Pr + 32 * b + 2 * tx, a0, a1, b0, b1);
        }
    }
}

__global__ __launch_bounds__(256, 3)
void attn_kernel(const float* __restrict__ q, const float* __restrict__ k) {
    extern __shared__ float sm[];
    float* ks = sm;                          // [64][210]  (transposed K)
    float* qs = ks + 64 * KS_STRIDE;         // [64][69]   (transposed Q, scaled)

    int h    = blockIdx.x;
    int nt   = blockIdx.y;
    int half = blockIdx.z / 3;
    int qh   = blockIdx.z - half * 3;
    int n = nt / 7, t = nt - n * 7;
    int tq = (half == 0) ? t + 1 : t;
    int tk = (half == 0) ? t : t + 1;
    int q0 = qh * 64;
    int nrows = (qh == 2) ? 68 : 64;

    const float* qb = q + ((size_t)(n * TDIM + tq) * LP1 + 1) * (HH * DD) + h * DD;
    const float* kb = k + ((size_t)(n * TDIM + tk) * LP1 + 1) * (HH * DD) + h * DD;
    float* P = ((half == 0) ? g_P1 : g_P2) + (size_t)nt * LL * LL;

    int tid = threadIdx.x;

    // K tile transposed: ks[d][kk] = k[kk][d]
    for (int i = tid; i < LL * DD; i += 256) {
        int kk = i >> 6, d = i & 63;
        ks[d * KS_STRIDE + kk] = kb[(size_t)kk * (HH * DD) + d];
    }
    // Q rows transposed, pre-scaled (conflict-free stride 69)
    for (int i = tid; i < nrows * DD; i += 256) {
        int qq = i >> 6, d = i & 63;
        qs[d * QS_STRIDE + qq] = qb[(size_t)(q0 + qq) * (HH * DD) + d] * 0.125f;
    }
    __syncthreads();

    int tx = tid & 15, ty = tid >> 4;

    // Main 64x196 GEMM over K=64: 4 rows x 7 col-pairs per thread, all valid.
    u64 acc[4][7];
    #pragma unroll
    for (int a = 0; a < 4; a++)
        #pragma unroll
        for (int b = 0; b < 7; b++) acc[a][b] = 0ULL;

    #pragma unroll 4
    for (int d = 0; d < 64; d++) {
        u64 ad[4], bv[7];
        #pragma unroll
        for (int a = 0; a < 4; a++) {
            float av = qs[d * QS_STRIDE + ty + 16 * a];
            ad[a] = pk2(av, av);
        }
        #pragma unroll
        for (int b = 0; b < 7; b++)
            bv[b] = *(const u64*)&ks[d * KS_STRIDE + 2 * tx + 32 * b];
        #pragma unroll
        for (int a = 0; a < 4; a++)
            #pragma unroll
            for (int b = 0; b < 7; b++)
                acc[a][b] = ffma2(ad[a], bv[b], acc[a][b]);
    }

    // Register softmax per row (half-warp owns a row), NO max subtraction.
    #pragma unroll
    for (int a = 0; a < 4; a++) {
        float e[14];
        #pragma unroll
        for (int b = 0; b < 7; b++) upk2(acc[a][b], e[2 * b], e[2 * b + 1]);

        bool v6 = (tx < 2);
        float s = 0.f;
        #pragma unroll
        for (int b = 0; b < 6; b++) {
            e[2 * b]     = __expf(e[2 * b]);
            e[2 * b + 1] = __expf(e[2 * b + 1]);
            s += e[2 * b] + e[2 * b + 1];
        }
        if (v6) {
            e[12] = __expf(e[12]);
            e[13] = __expf(e[13]);
            s += e[12] + e[13];
        }
        #pragma unroll
        for (int off = 8; off > 0; off >>= 1)
            s += __shfl_xor_sync(0xffffffffu, s, off);

        float inv = (1.f / 12.f) / s;
        u64 pv[7];
        #pragma unroll
        for (int b = 0; b < 7; b++)
            pv[b] = pk2(e[2 * b] * inv, e[2 * b + 1] * inv);
        store_row_v4(P + (size_t)(q0 + ty + 16 * a) * LL, pv, tx);
    }

    // Global 4-row tail (rows 192..195), qh==2 blocks only.
    if (qh == 2) {
        int qq2 = 64 + (ty & 3);
        u64 acct[7];
        #pragma unroll
        for (int b = 0; b < 7; b++) acct[b] = 0ULL;

        #pragma unroll 4
        for (int d = 0; d < 64; d++) {
            float av = qs[d * QS_STRIDE + qq2];
            u64 ad = pk2(av, av);
            #pragma unroll
            for (int b = 0; b < 7; b++)
                acct[b] = ffma2(ad, *(const u64*)&ks[d * KS_STRIDE + 2 * tx + 32 * b], acct[b]);
        }

        float e[14];
        #pragma unroll
        for (int b = 0; b < 7; b++) upk2(acct[b], e[2 * b], e[2 * b + 1]);

        bool v6 = (tx < 2);
        float s = 0.f;
        #pragma unroll
        for (int b = 0; b < 6; b++) {
            e[2 * b]     = __expf(e[2 * b]);
            e[2 * b + 1] = __expf(e[2 * b + 1]);
            s += e[2 * b] + e[2 * b + 1];
        }
        if (v6) {
            e[12] = __expf(e[12]);
            e[13] = __expf(e[13]);
            s += e[12] + e[13];
        }
        #pragma unroll
        for (int off = 8; off > 0; off >>= 1)
            s += __shfl_xor_sync(0xffffffffu, s, off);

        float inv = (1.f / 12.f) / s;
        u64 pv[7];
        #pragma unroll
        for (int b = 0; b < 7; b++)
            pv[b] = pk2(e[2 * b] * inv, e[2 * b + 1] * inv);
        #pragma unroll
        for (int b = 0; b < 7; b++) {
            u64 nb = __shfl_down_sync(0xffffffffu, pv[b], 1);
            if (ty < 4 && (tx & 1) == 0 && (b < 6 || tx == 0)) {
                float a0, a1, b0, b1;
                upk2(pv[b], a0, a1);
                upk2(nb,    b0, b1);
                red4(P + (size_t)(192 + ty) * LL + 32 * b + 2 * tx, a0, a1, b0, b1);
            }
        }
    }
}

// ---------------------------------------------------------------------------
// Kernel 2 — EXACT ROUND-13 VERSION (protected win): fused halves, np-merged,
// c-tile-paired, cp.async double-buffered gather.
// ---------------------------------------------------------------------------
#define TCo 64
#define WSF (98 * TCo)                  // 6272 floats per ws buffer
#define PSF (4 * LL * 8)                // 6272 floats per half
#define RED_U64 (4 * 32 * 8)            // 1024 u64 = 8192 B
#define O_SMEM_BYTES ((2*WSF + 2*PSF) * 4 + RED_U64 * 8)   // 108544 B

__global__ __launch_bounds__(256, 2)
void out_kernel(const float* __restrict__ w1, const float* __restrict__ w2,
                float* __restrict__ out) {
    extern __shared__ float sm[];
    float* psA = sm + 2 * WSF;          // [4][196*8]  slot tt = P1[t=tt-1], slot0=0
    float* psB = psA + PSF;             // [4][196*8]  slot tt = P2[tt],    slot7=0
    u64*   red = (u64*)(sm + 2 * WSF + 2 * PSF);

    int qq = blockIdx.y;
    int c0 = blockIdx.x * (2 * TCo);
    int tid = threadIdx.x;
    int pi = qq / 14, pj = qq - pi * 14;

    uint32_t ws_s0 = (uint32_t)__cvta_generic_to_shared(sm);

    #pragma unroll
    for (int r = 0; r < 28; r++) {
        int n_l = r / 7, t = r - n_l * 7;
        if (tid < LL) {
            size_t base = ((size_t)(n_l * 7 + t) * LL + qq) * LL + tid;
            psA[n_l * (LL * 8) + tid * 8 + t + 1] = g_P1[base];
            psB[n_l * (LL * 8) + tid * 8 + t]     = g_P2[base];
        }
    }
    if (tid < LL) {
        #pragma unroll
        for (int n_l = 0; n_l < 4; n_l++) {
            psA[n_l * (LL * 8) + tid * 8] = 0.f;
            psB[n_l * (LL * 8) + tid * 8 + 7] = 0.f;
        }
    }

    int wid = tid >> 5, lane = tid & 31;
    int n_l = wid >> 1, kq = wid & 1;
    int sub = lane >> 4, cl = lane & 15;
    int kst = kq * 49;

    auto gather = [&](int pp) {
        int ch = pp >> 2, ph = pp & 3;
        const float* w = (ph < 2) ? w1 : w2;
        int kbase = (ph & 1) * 98;
        int cc = c0 + ch * TCo;
        uint32_t dst = ws_s0 + (uint32_t)(pp & 1) * (WSF * 4);
        #pragma unroll
        for (int j = 0; j < 6; j++) {
            int i = tid + j * 256;
            int kk = i >> 4, cq = i & 15;
            int kg = kbase + kk;
            int ki = kg / 14, kj = kg - ki * 14;
            int idx = (pi - ki + 13) * 27 + (pj - kj + 13);
            cpa16(dst + (uint32_t)(kk * TCo + cq * 4) * 4,
                  w + (size_t)idx * CC + cc + cq * 4);
        }
        if (tid < 32) {
            int i = 1536 + tid;
            int kk = i >> 4, cq = i & 15;
            int kg = kbase + kk;
            int ki = kg / 14, kj = kg - ki * 14;
            int idx = (pi - ki + 13) * 27 + (pj - kj + 13);
            cpa16(dst + (uint32_t)(kk * TCo + cq * 4) * 4,
                  w + (size_t)idx * CC + cc + cq * 4);
        }
        CPA_COMMIT();
    };

    u64 acc[8];
    #pragma unroll
    for (int i = 0; i < 8; i++) acc[i] = 0ULL;

    gather(0);
    for (int pp = 0; pp < 8; pp++) {
        if (pp < 7) { gather(pp + 1); CPA_WAIT(1); }
        else        { CPA_WAIT(0); }
        __syncthreads();

        int ph = pp & 3, ch = pp >> 2;
        const float* ps = ((ph < 2) ? psA : psB) + n_l * (LL * 8);
        int kbase = (ph & 1) * 98;
        const float* ws = sm + (pp & 1) * WSF;

        #pragma unroll 7
        for (int kl = kst; kl < kst + 49; kl++) {
            float4 wv = *(const float4*)&ws[kl * TCo + cl * 4];
            ulonglong2 pr = *(const ulonglong2*)&ps[(kbase + kl) * 8 + sub * 4];
            u64 b0 = pk2(wv.x, wv.x), b1 = pk2(wv.y, wv.y);
            u64 b2 = pk2(wv.z, wv.z), b3 = pk2(wv.w, wv.w);
            acc[0] = ffma2(pr.x, b0, acc[0]);  acc[1] = ffma2(pr.y, b0, acc[1]);
            acc[2] = ffma2(pr.x, b1, acc[2]);  acc[3] = ffma2(pr.y, b1, acc[3]);
            acc[4] = ffma2(pr.x, b2, acc[4]);  acc[5] = ffma2(pr.y, b2, acc[5]);
            acc[6] = ffma2(pr.x, b3, acc[6]);  acc[7] = ffma2(pr.y, b3, acc[7]);
        }

        bool epi = ((pp & 3) == 3);
        if (epi && kq) {
            int base = (n_l * 32 + lane) * 8;
            #pragma unroll
            for (int j = 0; j < 8; j++) red[base + j] = acc[j];
        }
        __syncthreads();

        if (epi) {
            if (kq == 0) {
                int base = (n_l * 32 + lane) * 8;
                #pragma unroll
                for (int j = 0; j < 8; j++) acc[j] = fadd2(acc[j], red[base + j]);

                int cc = c0 + ch * TCo;
                float a[16];
                #pragma unroll
                for (int i = 0; i < 8; i++) upk2(acc[i], a[2 * i], a[2 * i + 1]);
                #pragma unroll
                for (int tl = 0; tl < 4; tl++) {
                    int tt = sub * 4 + tl;
                    int tp = tl >> 1, hi = tl & 1;
                    float4 o4;
                    o4.x = a[(0 * 2 + tp) * 2 + hi];
                    o4.y = a[(1 * 2 + tp) * 2 + hi];
                    o4.z = a[(2 * 2 + tp) * 2 + hi];
                    o4.w = a[(3 * 2 + tp) * 2 + hi];
                    *(float4*)(out + ((size_t)(n_l * TDIM + tt) * LP1 + qq + 1) * CC
                               + cc + cl * 4) = o4;
                }
            }
            #pragma unroll
            for (int i = 0; i < 8; i++) acc[i] = 0ULL;
        }
    }
}

// ---------------------------------------------------------------------------
extern "C" void kernel_launch(void* const* d_in, const int* in_sizes, int n_in,
                              void* d_out, int out_size) {
    const float* q  = (const float*)d_in[0];
    const float* k  = (const float*)d_in[1];
    const float* w1 = (const float*)d_in[2];
    const float* w2 = (const float*)d_in[3];
    float* out = (float*)d_out;

    cudaFuncSetAttribute(attn_kernel, cudaFuncAttributeMaxDynamicSharedMemorySize, A_SMEM_BYTES);
    cudaFuncSetAttribute(out_kernel,  cudaFuncAttributeMaxDynamicSharedMemorySize, O_SMEM_BYTES);

    zero_kernel<<<2048, 256>>>(out);
    attn_kernel<<<dim3(HH, NT, 6), 256, A_SMEM_BYTES>>>(q, k);
    out_kernel<<<dim3(CC / (2 * TCo), LL, 1), 256, O_SMEM_BYTES>>>(w1, w2, out);
}

// round 16
// speedup vs baseline: 1.2313x; 1.0326x over previous
#include <cuda_runtime.h>
#include <math.h>
#include <stdint.h>

#define NB 4
#define TDIM 8
#define LP1 197
#define HH 12
#define DD 64
#define CC 768
#define LL 196
#define NT 28   // NB*(TDIM-1)

typedef unsigned long long u64;

__device__ __forceinline__ u64 pk2(float lo, float hi) {
    u64 r; asm("mov.b64 %0,{%1,%2};" : "=l"(r) : "f"(lo), "f"(hi)); return r;
}
__device__ __forceinline__ void upk2(u64 v, float& lo, float& hi) {
    asm("mov.b64 {%0,%1},%2;" : "=f"(lo), "=f"(hi) : "l"(v));
}
__device__ __forceinline__ u64 ffma2(u64 a, u64 b, u64 c) {
    u64 d; asm("fma.rn.f32x2 %0,%1,%2,%3;" : "=l"(d) : "l"(a), "l"(b), "l"(c)); return d;
}
__device__ __forceinline__ u64 fadd2(u64 a, u64 b) {
    u64 d; asm("add.rn.f32x2 %0,%1,%2;" : "=l"(d) : "l"(a), "l"(b)); return d;
}
__device__ __forceinline__ void red4(float* p, float a, float b, float c, float d) {
    asm volatile("red.global.add.v4.f32 [%0], {%1,%2,%3,%4};"
                 :: "l"(p), "f"(a), "f"(b), "f"(c), "f"(d) : "memory");
}
__device__ __forceinline__ void cpa16(uint32_t s, const void* g) {
    asm volatile("cp.async.cg.shared.global [%0], [%1], 16;" :: "r"(s), "l"(g) : "memory");
}
#define CPA_COMMIT() asm volatile("cp.async.commit_group;" ::: "memory")
#define CPA_WAIT(n)  asm volatile("cp.async.wait_group %0;" :: "n"(n) : "memory")

// Scratch: head-averaged attention probabilities for each half.
__device__ __align__(16) float g_P1[NT * LL * LL];
__device__ __align__(16) float g_P2[NT * LL * LL];

// ---------------------------------------------------------------------------
// Kernel 0: zero P scratch and cls rows of out — float4 vectorized.
// ---------------------------------------------------------------------------
__global__ void zero_kernel(float* __restrict__ out) {
    size_t stride = (size_t)gridDim.x * blockDim.x;
    size_t i = (size_t)blockIdx.x * blockDim.x + threadIdx.x;
    float4 z = make_float4(0.f, 0.f, 0.f, 0.f);
    float4* p1 = (float4*)g_P1;
    float4* p2 = (float4*)g_P2;
    const size_t np4 = (size_t)NT * LL * LL / 4;
    for (size_t j = i; j < np4; j += stride) { p1[j] = z; p2[j] = z; }
    const size_t nc4 = (size_t)NB * TDIM * (CC / 4);
    float4* o4 = (float4*)out;
    for (size_t j = i; j < nc4; j += stride) {
        size_t nt = j / (CC / 4), c = j - nt * (CC / 4);
        o4[nt * ((size_t)LP1 * CC / 4) + c] = z;
    }
}

// ---------------------------------------------------------------------------
// Kernel 1: attention — EXACT ROUND-13 VERSION (protected local optimum:
// z=3 chunking, column-major stride-69 Q, max-subtracted register softmax,
// v4 paired REDG).  Both softmax-shortening variants regressed.
// ---------------------------------------------------------------------------
#define KS_STRIDE 210
#define QS_STRIDE 69
#define A_SMEM_BYTES ((64*KS_STRIDE + 64*QS_STRIDE) * 4)   // 71424 B

__device__ __forceinline__ void store_row_v4(float* Pr, const u64* pv, int tx) {
    #pragma unroll
    for (int b = 0; b < 7; b++) {
        u64 nb = __shfl_down_sync(0xffffffffu, pv[b], 1);
        if ((tx & 1) == 0 && (b < 6 || tx == 0)) {
            float a0, a1, b0, b1;
            upk2(pv[b], a0, a1);
            upk2(nb,    b0, b1);
            red4(Pr + 32 * b + 2 * tx, a0, a1, b0, b1);
        }
    }
}

__global__ __launch_bounds__(256, 3)
void attn_kernel(const float* __restrict__ q, const float* __restrict__ k) {
    extern __shared__ float sm[];
    float* ks = sm;                          // [64][210]
    float* qs = ks + 64 * KS_STRIDE;         // [64][69]

    int h    = blockIdx.x;
    int nt   = blockIdx.y;
    int half = blockIdx.z / 3;
    int qh   = blockIdx.z - half * 3;
    int n = nt / 7, t = nt - n * 7;
    int tq = (half == 0) ? t + 1 : t;
    int tk = (half == 0) ? t : t + 1;
    int q0 = qh * 64;
    int nrows = (qh == 2) ? 68 : 64;

    const float* qb = q + ((size_t)(n * TDIM + tq) * LP1 + 1) * (HH * DD) + h * DD;
    const float* kb = k + ((size_t)(n * TDIM + tk) * LP1 + 1) * (HH * DD) + h * DD;
    float* P = ((half == 0) ? g_P1 : g_P2) + (size_t)nt * LL * LL;

    int tid = threadIdx.x;

    for (int i = tid; i < LL * DD; i += 256) {
        int kk = i >> 6, d = i & 63;
        ks[d * KS_STRIDE + kk] = kb[(size_t)kk * (HH * DD) + d];
    }
    for (int i = tid; i < nrows * DD; i += 256) {
        int qq = i >> 6, d = i & 63;
        qs[d * QS_STRIDE + qq] = qb[(size_t)(q0 + qq) * (HH * DD) + d] * 0.125f;
    }
    __syncthreads();

    int tx = tid & 15, ty = tid >> 4;

    u64 acc[4][7];
    #pragma unroll
    for (int a = 0; a < 4; a++)
        #pragma unroll
        for (int b = 0; b < 7; b++) acc[a][b] = 0ULL;

    #pragma unroll 4
    for (int d = 0; d < 64; d++) {
        u64 ad[4], bv[7];
        #pragma unroll
        for (int a = 0; a < 4; a++) {
            float av = qs[d * QS_STRIDE + ty + 16 * a];
            ad[a] = pk2(av, av);
        }
        #pragma unroll
        for (int b = 0; b < 7; b++)
            bv[b] = *(const u64*)&ks[d * KS_STRIDE + 2 * tx + 32 * b];
        #pragma unroll
        for (int a = 0; a < 4; a++)
            #pragma unroll
            for (int b = 0; b < 7; b++)
                acc[a][b] = ffma2(ad[a], bv[b], acc[a][b]);
    }

    #pragma unroll
    for (int a = 0; a < 4; a++) {
        float e[14];
        #pragma unroll
        for (int b = 0; b < 7; b++) upk2(acc[a][b], e[2 * b], e[2 * b + 1]);

        bool v6 = (tx < 2);
        float mx = -1e30f;
        #pragma unroll
        for (int b = 0; b < 6; b++) mx = fmaxf(mx, fmaxf(e[2 * b], e[2 * b + 1]));
        if (v6) mx = fmaxf(mx, fmaxf(e[12], e[13]));
        #pragma unroll
        for (int off = 8; off > 0; off >>= 1)
            mx = fmaxf(mx, __shfl_xor_sync(0xffffffffu, mx, off));

        float s = 0.f;
        #pragma unroll
        for (int b = 0; b < 6; b++) {
            e[2 * b]     = __expf(e[2 * b] - mx);
            e[2 * b + 1] = __expf(e[2 * b + 1] - mx);
            s += e[2 * b] + e[2 * b + 1];
        }
        if (v6) {
            e[12] = __expf(e[12] - mx);
            e[13] = __expf(e[13] - mx);
            s += e[12] + e[13];
        }
        #pragma unroll
        for (int off = 8; off > 0; off >>= 1)
            s += __shfl_xor_sync(0xffffffffu, s, off);

        float inv = (1.f / 12.f) / s;
        u64 pv[7];
        #pragma unroll
        for (int b = 0; b < 7; b++)
            pv[b] = pk2(e[2 * b] * inv, e[2 * b + 1] * inv);
        store_row_v4(P + (size_t)(q0 + ty + 16 * a) * LL, pv, tx);
    }

    if (qh == 2) {
        int qq2 = 64 + (ty & 3);
        u64 acct[7];
        #pragma unroll
        for (int b = 0; b < 7; b++) acct[b] = 0ULL;

        #pragma unroll 4
        for (int d = 0; d < 64; d++) {
            float av = qs[d * QS_STRIDE + qq2];
            u64 ad = pk2(av, av);
            #pragma unroll
            for (int b = 0; b < 7; b++)
                acct[b] = ffma2(ad, *(const u64*)&ks[d * KS_STRIDE + 2 * tx + 32 * b], acct[b]);
        }

        float e[14];
        #pragma unroll
        for (int b = 0; b < 7; b++) upk2(acct[b], e[2 * b], e[2 * b + 1]);

        bool v6 = (tx < 2);
        float mx = -1e30f;
        #pragma unroll
        for (int b = 0; b < 6; b++) mx = fmaxf(mx, fmaxf(e[2 * b], e[2 * b + 1]));
        if (v6) mx = fmaxf(mx, fmaxf(e[12], e[13]));
        #pragma unroll
        for (int off = 8; off > 0; off >>= 1)
            mx = fmaxf(mx, __shfl_xor_sync(0xffffffffu, mx, off));

        float s = 0.f;
        #pragma unroll
        for (int b = 0; b < 6; b++) {
            e[2 * b]     = __expf(e[2 * b] - mx);
            e[2 * b + 1] = __expf(e[2 * b + 1] - mx);
            s += e[2 * b] + e[2 * b + 1];
        }
        if (v6) {
            e[12] = __expf(e[12] - mx);
            e[13] = __expf(e[13] - mx);
            s += e[12] + e[13];
        }
        #pragma unroll
        for (int off = 8; off > 0; off >>= 1)
            s += __shfl_xor_sync(0xffffffffu, s, off);

        float inv = (1.f / 12.f) / s;
        u64 pv[7];
        #pragma unroll
        for (int b = 0; b < 7; b++)
            pv[b] = pk2(e[2 * b] * inv, e[2 * b + 1] * inv);
        #pragma unroll
        for (int b = 0; b < 7; b++) {
            u64 nb = __shfl_down_sync(0xffffffffu, pv[b], 1);
            if (ty < 4 && (tx & 1) == 0 && (b < 6 || tx == 0)) {
                float a0, a1, b0, b1;
                upk2(pv[b], a0, a1);
                upk2(nb,    b0, b1);
                red4(P + (size_t)(192 + ty) * LL + 32 * b + 2 * tx, a0, a1, b0, b1);
            }
        }
    }
}

// ---------------------------------------------------------------------------
// Kernel 2 — R13 structure + ONE change: per-block precomputed gather row
// offsets widx[196] = IDX[qq][kg]*CC in smem (784B).  Replaces the per-cpa16
// div-by-14 + index chain (~400 ALU inst/thread) with a single LDS + add.
// One extra __syncthreads at block start (widx visibility before gather(0)).
// ---------------------------------------------------------------------------
#define TCo 64
#define WSF (98 * TCo)                  // 6272 floats per ws buffer
#define PSF (4 * LL * 8)                // 6272 floats per half
#define RED_U64 (4 * 32 * 8)            // 1024 u64 = 8192 B
#define O_SMEM_BYTES ((2*WSF + 2*PSF) * 4 + RED_U64 * 8 + LL * 4)   // 109328 B

__global__ __launch_bounds__(256, 2)
void out_kernel(const float* __restrict__ w1, const float* __restrict__ w2,
                float* __restrict__ out) {
    extern __shared__ float sm[];
    float* psA = sm + 2 * WSF;          // [4][196*8]  slot tt = P1[t=tt-1], slot0=0
    float* psB = psA + PSF;             // [4][196*8]  slot tt = P2[tt],    slot7=0
    u64*   red = (u64*)(sm + 2 * WSF + 2 * PSF);
    int*   widx = (int*)(red + RED_U64);   // [196]  IDX[qq][kg]*CC

    int qq = blockIdx.y;
    int c0 = blockIdx.x * (2 * TCo);
    int tid = threadIdx.x;
    int pi = qq / 14, pj = qq - pi * 14;

    uint32_t ws_s0 = (uint32_t)__cvta_generic_to_shared(sm);

    // Precompute gather row offsets (constant per block).
    for (int i = tid; i < LL; i += 256) {
        int ki = i / 14, kj = i - ki * 14;
        widx[i] = ((pi - ki + 13) * 27 + (pj - kj + 13)) * CC;
    }

    // Stage P rows t-strided for all 4 n, both halves (once per block).
    #pragma unroll
    for (int r = 0; r < 28; r++) {
        int n_l = r / 7, t = r - n_l * 7;
        if (tid < LL) {
            size_t base = ((size_t)(n_l * 7 + t) * LL + qq) * LL + tid;
            psA[n_l * (LL * 8) + tid * 8 + t + 1] = g_P1[base];
            psB[n_l * (LL * 8) + tid * 8 + t]     = g_P2[base];
        }
    }
    if (tid < LL) {
        #pragma unroll
        for (int n_l = 0; n_l < 4; n_l++) {
            psA[n_l * (LL * 8) + tid * 8] = 0.f;
            psB[n_l * (LL * 8) + tid * 8 + 7] = 0.f;
        }
    }
    __syncthreads();   // widx (and ps) visible before gather(0)

    int wid = tid >> 5, lane = tid & 31;
    int n_l = wid >> 1, kq = wid & 1;
    int sub = lane >> 4, cl = lane & 15;
    int kst = kq * 49;

    auto gather = [&](int pp) {
        int ch = pp >> 2, ph = pp & 3;
        const float* w = (ph < 2) ? w1 : w2;
        int kbase = (ph & 1) * 98;
        int cc = c0 + ch * TCo;
        uint32_t dst = ws_s0 + (uint32_t)(pp & 1) * (WSF * 4);
        #pragma unroll
        for (int j = 0; j < 6; j++) {
            int i = tid + j * 256;
            int kk = i >> 4, cq = i & 15;
            cpa16(dst + (uint32_t)(kk * TCo + cq * 4) * 4,
                  w + widx[kbase + kk] + cc + cq * 4);
        }
        if (tid < 32) {
            int i = 1536 + tid;
            int kk = i >> 4, cq = i & 15;
            cpa16(dst + (uint32_t)(kk * TCo + cq * 4) * 4,
                  w + widx[kbase + kk] + cc + cq * 4);
        }
        CPA_COMMIT();
    };

    u64 acc[8];
    #pragma unroll
    for (int i = 0; i < 8; i++) acc[i] = 0ULL;

    gather(0);
    for (int pp = 0; pp < 8; pp++) {
        if (pp < 7) { gather(pp + 1); CPA_WAIT(1); }
        else        { CPA_WAIT(0); }
        __syncthreads();

        int ph = pp & 3, ch = pp >> 2;
        const float* ps = ((ph < 2) ? psA : psB) + n_l * (LL * 8);
        int kbase = (ph & 1) * 98;
        const float* ws = sm + (pp & 1) * WSF;

        #pragma unroll 7
        for (int kl = kst; kl < kst + 49; kl++) {
            float4 wv = *(const float4*)&ws[kl * TCo + cl * 4];
            ulonglong2 pr = *(const ulonglong2*)&ps[(kbase + kl) * 8 + sub * 4];
            u64 b0 = pk2(wv.x, wv.x), b1 = pk2(wv.y, wv.y);
            u64 b2 = pk2(wv.z, wv.z), b3 = pk2(wv.w, wv.w);
            acc[0] = ffma2(pr.x, b0, acc[0]);  acc[1] = ffma2(pr.y, b0, acc[1]);
            acc[2] = ffma2(pr.x, b1, acc[2]);  acc[3] = ffma2(pr.y, b1, acc[3]);
            acc[4] = ffma2(pr.x, b2, acc[4]);  acc[5] = ffma2(pr.y, b2, acc[5]);
            acc[6] = ffma2(pr.x, b3, acc[6]);  acc[7] = ffma2(pr.y, b3, acc[7]);
        }

        bool epi = ((pp & 3) == 3);
        if (epi && kq) {
            int base = (n_l * 32 + lane) * 8;
            #pragma unroll
            for (int j = 0; j < 8; j++) red[base + j] = acc[j];
        }
        __syncthreads();

        if (epi) {
            if (kq == 0) {
                int base = (n_l * 32 + lane) * 8;
                #pragma unroll
                for (int j = 0; j < 8; j++) acc[j] = fadd2(acc[j], red[base + j]);

                int cc = c0 + ch * TCo;
                float a[16];
                #pragma unroll
                for (int i = 0; i < 8; i++) upk2(acc[i], a[2 * i], a[2 * i + 1]);
                #pragma unroll
                for (int tl = 0; tl < 4; tl++) {
                    int tt = sub * 4 + tl;
                    int tp = tl >> 1, hi = tl & 1;
                    float4 o4;
                    o4.x = a[(0 * 2 + tp) * 2 + hi];
                    o4.y = a[(1 * 2 + tp) * 2 + hi];
                    o4.z = a[(2 * 2 + tp) * 2 + hi];
                    o4.w = a[(3 * 2 + tp) * 2 + hi];
                    *(float4*)(out + ((size_t)(n_l * TDIM + tt) * LP1 + qq + 1) * CC
                               + cc + cl * 4) = o4;
                }
            }
            #pragma unroll
            for (int i = 0; i < 8; i++) acc[i] = 0ULL;
        }
    }
}

// ---------------------------------------------------------------------------
extern "C" void kernel_launch(void* const* d_in, const int* in_sizes, int n_in,
                              void* d_out, int out_size) {
    const float* q  = (const float*)d_in[0];
    const float* k  = (const float*)d_in[1];
    const float* w1 = (const float*)d_in[2];
    const float* w2 = (const float*)d_in[3];
    float* out = (float*)d_out;

    cudaFuncSetAttribute(attn_kernel, cudaFuncAttributeMaxDynamicSharedMemorySize, A_SMEM_BYTES);
    cudaFuncSetAttribute(out_kernel,  cudaFuncAttributeMaxDynamicSharedMemorySize, O_SMEM_BYTES);

    zero_kernel<<<512, 256>>>(out);
    attn_kernel<<<dim3(HH, NT, 6), 256, A_SMEM_BYTES>>>(q, k);
    out_kernel<<<dim3(CC / (2 * TCo), LL, 1), 256, O_SMEM_BYTES>>>(w1, w2, out);
}

// round 17
// speedup vs baseline: 1.4945x; 1.2137x over previous
#include <cuda_runtime.h>
#include <cuda_bf16.h>
#include <math.h>
#include <stdint.h>

#define NB 4
#define TDIM 8
#define LP1 197
#define HH 12
#define DD 64
#define CC 768
#define LL 196
#define NT 28   // NB*(TDIM-1)

typedef unsigned long long u64;

__device__ __forceinline__ u64 pk2(float lo, float hi) {
    u64 r; asm("mov.b64 %0,{%1,%2};" : "=l"(r) : "f"(lo), "f"(hi)); return r;
}
__device__ __forceinline__ void upk2(u64 v, float& lo, float& hi) {
    asm("mov.b64 {%0,%1},%2;" : "=f"(lo), "=f"(hi) : "l"(v));
}
__device__ __forceinline__ u64 ffma2(u64 a, u64 b, u64 c) {
    u64 d; asm("fma.rn.f32x2 %0,%1,%2,%3;" : "=l"(d) : "l"(a), "l"(b), "l"(c)); return d;
}
__device__ __forceinline__ u64 fadd2(u64 a, u64 b) {
    u64 d; asm("add.rn.f32x2 %0,%1,%2;" : "=l"(d) : "l"(a), "l"(b)); return d;
}
__device__ __forceinline__ void red4(float* p, float a, float b, float c, float d) {
    asm volatile("red.global.add.v4.f32 [%0], {%1,%2,%3,%4};"
                 :: "l"(p), "f"(a), "f"(b), "f"(c), "f"(d) : "memory");
}
__device__ __forceinline__ void cpa16(uint32_t s, const void* g) {
    asm volatile("cp.async.cg.shared.global [%0], [%1], 16;" :: "r"(s), "l"(g) : "memory");
}
#define CPA_COMMIT() asm volatile("cp.async.commit_group;" ::: "memory")
#define CPA_WAIT(n)  asm volatile("cp.async.wait_group %0;" :: "n"(n) : "memory")

// mma.sync bf16 helpers (warp tensor-core path, fp32 accumulate)
__device__ __forceinline__ void mma16816(float* d, const uint32_t* a, const uint32_t* b) {
    asm volatile(
        "mma.sync.aligned.m16n8k16.row.col.f32.bf16.bf16.f32 "
        "{%0,%1,%2,%3}, {%4,%5,%6,%7}, {%8,%9}, {%0,%1,%2,%3};"
        : "+f"(d[0]), "+f"(d[1]), "+f"(d[2]), "+f"(d[3])
        : "r"(a[0]), "r"(a[1]), "r"(a[2]), "r"(a[3]), "r"(b[0]), "r"(b[1]));
}
__device__ __forceinline__ void ldsm4(uint32_t* r, uint32_t addr) {
    asm volatile("ldmatrix.sync.aligned.m8n8.x4.shared.b16 {%0,%1,%2,%3}, [%4];"
                 : "=r"(r[0]), "=r"(r[1]), "=r"(r[2]), "=r"(r[3]) : "r"(addr));
}
__device__ __forceinline__ void ldsm2(uint32_t* r, uint32_t addr) {
    asm volatile("ldmatrix.sync.aligned.m8n8.x2.shared.b16 {%0,%1}, [%2];"
                 : "=r"(r[0]), "=r"(r[1]) : "r"(addr));
}

// Scratch: head-averaged attention probabilities for each half.
__device__ __align__(16) float g_P1[NT * LL * LL];
__device__ __align__(16) float g_P2[NT * LL * LL];

// ---------------------------------------------------------------------------
// Kernel 0: zero P scratch and the cls (q=0) rows of out.
// ---------------------------------------------------------------------------
__global__ void zero_kernel(float* __restrict__ out) {
    size_t stride = (size_t)gridDim.x * blockDim.x;
    size_t i = (size_t)blockIdx.x * blockDim.x + threadIdx.x;
    const size_t np = (size_t)NT * LL * LL;
    for (size_t j = i; j < np; j += stride) { g_P1[j] = 0.f; g_P2[j] = 0.f; }
    const size_t ncls = (size_t)NB * TDIM * CC;
    for (size_t j = i; j < ncls; j += stride) {
        size_t nt = j / CC, c = j - nt * CC;
        out[(nt * LP1) * CC + c] = 0.f;
    }
}

// ---------------------------------------------------------------------------
// Kernel 1: attention, SPLIT-BF16 TENSOR-CORE score GEMM.
// Block = (h, nt, half*3+qh), 256 threads, 2 CTAs/SM (84.2KB smem).
// K staged bf16 hi/lo [208][72] (rows>=196 zero; stride 144B -> conflict-free
// ldmatrix); Q staged bf16 hi/lo [80][72] (scaled by 0.125; pad rows zero).
// 8 warps = 4 m-tiles x 2 n-halves; score = Ahi*Bhi + Ahi*Blo + Alo*Bhi
// (fp32 accum, ~1e-4 accuracy).  Register softmax epilogue: quad-shuffle
// max/sum + cross-n-half combine via smem; paired-lane red4 into P.
// qh==2: rows 128-195 via 4 m-tiles + a 5th-tile pass on warps 0-1.
// ---------------------------------------------------------------------------
#define KR 72                            // bf16 row stride (144B)
#define A_SMEM_BYTES (2*(208*KR + 80*KR)*2 + 2*160*4)   // 84224

__global__ __launch_bounds__(256, 2)
void attn_kernel(const float* __restrict__ q, const float* __restrict__ k) {
    extern __shared__ char smc[];
    __nv_bfloat16* KH = (__nv_bfloat16*)smc;         // [208][72]
    __nv_bfloat16* KL = KH + 208 * KR;
    __nv_bfloat16* QH = KL + 208 * KR;               // [80][72]
    __nv_bfloat16* QL = QH + 80 * KR;
    float* maxb = (float*)(QL + 80 * KR);            // [2][80]
    float* sumb = maxb + 160;                        // [2][80]

    int h    = blockIdx.x;
    int nt   = blockIdx.y;
    int half = blockIdx.z / 3;
    int qh   = blockIdx.z - half * 3;
    int n = nt / 7, t = nt - n * 7;
    int tq = (half == 0) ? t + 1 : t;
    int tk = (half == 0) ? t : t + 1;
    int q0 = qh * 64;
    int nrows = (qh == 2) ? 68 : 64;
    int srows = (qh == 2) ? 80 : 64;

    const float* qb = q + ((size_t)(n * TDIM + tq) * LP1 + 1) * (HH * DD) + h * DD;
    const float* kb = k + ((size_t)(n * TDIM + tk) * LP1 + 1) * (HH * DD) + h * DD;
    float* P = ((half == 0) ? g_P1 : g_P2) + (size_t)nt * LL * LL;

    int tid = threadIdx.x, lane = tid & 31, wid = tid >> 5;

    // Stage K bf16 hi/lo (float4 granularity), rows >= 196 zero.
    for (int i = tid; i < 208 * 16; i += 256) {
        int kk = i >> 4, d4 = i & 15;
        float4 v = make_float4(0.f, 0.f, 0.f, 0.f);
        if (kk < LL) v = *(const float4*)(kb + (size_t)kk * (HH * DD) + d4 * 4);
        __nv_bfloat162 h01 = __floats2bfloat162_rn(v.x, v.y);
        __nv_bfloat162 h23 = __floats2bfloat162_rn(v.z, v.w);
        float2 f01 = __bfloat1622float2(h01);
        float2 f23 = __bfloat1622float2(h23);
        __nv_bfloat162 l01 = __floats2bfloat162_rn(v.x - f01.x, v.y - f01.y);
        __nv_bfloat162 l23 = __floats2bfloat162_rn(v.z - f23.x, v.w - f23.y);
        *(__nv_bfloat162*)&KH[kk * KR + d4 * 4]     = h01;
        *(__nv_bfloat162*)&KH[kk * KR + d4 * 4 + 2] = h23;
        *(__nv_bfloat162*)&KL[kk * KR + d4 * 4]     = l01;
        *(__nv_bfloat162*)&KL[kk * KR + d4 * 4 + 2] = l23;
    }
    // Stage Q bf16 hi/lo, pre-scaled; pad rows zero.
    for (int i = tid; i < srows * 16; i += 256) {
        int qq = i >> 4, d4 = i & 15;
        float4 v = make_float4(0.f, 0.f, 0.f, 0.f);
        if (qq < nrows) {
            v = *(const float4*)(qb + (size_t)(q0 + qq) * (HH * DD) + d4 * 4);
            v.x *= 0.125f; v.y *= 0.125f; v.z *= 0.125f; v.w *= 0.125f;
        }
        __nv_bfloat162 h01 = __floats2bfloat162_rn(v.x, v.y);
        __nv_bfloat162 h23 = __floats2bfloat162_rn(v.z, v.w);
        float2 f01 = __bfloat1622float2(h01);
        float2 f23 = __bfloat1622float2(h23);
        __nv_bfloat162 l01 = __floats2bfloat162_rn(v.x - f01.x, v.y - f01.y);
        __nv_bfloat162 l23 = __floats2bfloat162_rn(v.z - f23.x, v.w - f23.y);
        *(__nv_bfloat162*)&QH[qq * KR + d4 * 4]     = h01;
        *(__nv_bfloat162*)&QH[qq * KR + d4 * 4 + 2] = h23;
        *(__nv_bfloat162*)&QL[qq * KR + d4 * 4]     = l01;
        *(__nv_bfloat162*)&QL[qq * KR + d4 * 4 + 2] = l23;
    }
    __syncthreads();

    uint32_t khA = (uint32_t)__cvta_generic_to_shared(KH);
    uint32_t klA = (uint32_t)__cvta_generic_to_shared(KL);
    uint32_t qhA = (uint32_t)__cvta_generic_to_shared(QH);
    uint32_t qlA = (uint32_t)__cvta_generic_to_shared(QL);

    int g = lane & 3;

    for (int pass = 0; pass < 2; pass++) {
        if (pass == 1 && qh != 2) break;   // block-uniform

        int mt, nh;
        bool active;
        if (pass == 0) { mt = wid >> 1; nh = wid & 1; active = true; }
        else           { mt = 4;        nh = wid;     active = (wid < 2); }

        float acc[13][4];
        if (active) {
            #pragma unroll
            for (int jj = 0; jj < 13; jj++)
                #pragma unroll
                for (int r = 0; r < 4; r++) acc[jj][r] = 0.f;

            // A fragments (Q): hi and lo for all 4 k-steps.
            uint32_t ah[4][4], al[4][4];
            uint32_t aoff = (uint32_t)((mt * 16 + (lane & 15)) * (KR * 2) + (lane >> 4) * 16);
            #pragma unroll
            for (int ks = 0; ks < 4; ks++) {
                ldsm4(ah[ks], qhA + aoff + ks * 32);
                ldsm4(al[ks], qlA + aoff + ks * 32);
            }

            uint32_t boff0 = (uint32_t)((lane & 7) * (KR * 2) + ((lane >> 3) & 1) * 16);
            #pragma unroll
            for (int jj = 0; jj < 13; jj++) {
                if (!(nh == 1 && jj == 12)) {
                    int j = nh * 13 + jj;
                    uint32_t brow = boff0 + (uint32_t)(j * 8) * (KR * 2);
                    #pragma unroll
                    for (int ks = 0; ks < 4; ks++) {
                        uint32_t bh[2], bl[2];
                        ldsm2(bh, khA + brow + ks * 32);
                        ldsm2(bl, klA + brow + ks * 32);
                        mma16816(acc[jj], ah[ks], bh);
                        mma16816(acc[jj], ah[ks], bl);
                        mma16816(acc[jj], al[ks], bh);
                    }
                }
            }
        }

        int r0 = mt * 16 + (lane >> 2);    // local row (r1 = r0+8)

        // Row max (local -> quad -> smem)
        if (active) {
            float m0 = -1e30f, m1 = -1e30f;
            #pragma unroll
            for (int jj = 0; jj < 13; jj++) {
                if (nh == 1 && jj == 12) continue;
                bool v = (nh == 0) || (jj < 11) || (g < 2);
                if (v) {
                    m0 = fmaxf(m0, fmaxf(acc[jj][0], acc[jj][1]));
                    m1 = fmaxf(m1, fmaxf(acc[jj][2], acc[jj][3]));
                }
            }
            #pragma unroll
            for (int off = 1; off <= 2; off <<= 1) {
                m0 = fmaxf(m0, __shfl_xor_sync(0xffffffffu, m0, off));
                m1 = fmaxf(m1, __shfl_xor_sync(0xffffffffu, m1, off));
            }
            if (g == 0) { maxb[nh * 80 + r0] = m0; maxb[nh * 80 + r0 + 8] = m1; }
        }
        __syncthreads();

        // exp + row sum (local -> quad -> smem)
        if (active) {
            float gm0 = fmaxf(maxb[r0], maxb[80 + r0]);
            float gm1 = fmaxf(maxb[r0 + 8], maxb[80 + r0 + 8]);
            float s0 = 0.f, s1 = 0.f;
            #pragma unroll
            for (int jj = 0; jj < 13; jj++) {
                if (nh == 1 && jj == 12) continue;
                bool v = (nh == 0) || (jj < 11) || (g < 2);
                if (v) {
                    acc[jj][0] = __expf(acc[jj][0] - gm0);
                    acc[jj][1] = __expf(acc[jj][1] - gm0);
                    acc[jj][2] = __expf(acc[jj][2] - gm1);
                    acc[jj][3] = __expf(acc[jj][3] - gm1);
                    s0 += acc[jj][0] + acc[jj][1];
                    s1 += acc[jj][2] + acc[jj][3];
                } else {
                    acc[jj][0] = acc[jj][1] = acc[jj][2] = acc[jj][3] = 0.f;
                }
            }
            #pragma unroll
            for (int off = 1; off <= 2; off <<= 1) {
                s0 += __shfl_xor_sync(0xffffffffu, s0, off);
                s1 += __shfl_xor_sync(0xffffffffu, s1, off);
            }
            if (g == 0) { sumb[nh * 80 + r0] = s0; sumb[nh * 80 + r0 + 8] = s1; }
        }
        __syncthreads();

        // Normalize + paired-lane red4 into P.
        if (active) {
            float inv0 = (1.f / 12.f) / (sumb[r0] + sumb[80 + r0]);
            float inv1 = (1.f / 12.f) / (sumb[r0 + 8] + sumb[80 + r0 + 8]);
            bool ok0 = (q0 + r0) < LL;
            bool ok1 = (q0 + r0 + 8) < LL;
            float* P0 = P + (size_t)(q0 + r0) * LL;
            float* P1 = P + (size_t)(q0 + r0 + 8) * LL;
            #pragma unroll
            for (int jj = 0; jj < 13; jj++) {
                if (nh == 1 && jj == 12) continue;
                int colb = (nh * 13 + jj) * 8 + g * 2;
                float e0 = acc[jj][0] * inv0, e1 = acc[jj][1] * inv0;
                float e2 = acc[jj][2] * inv1, e3 = acc[jj][3] * inv1;
                float f0 = __shfl_down_sync(0xffffffffu, e0, 1);
                float f1 = __shfl_down_sync(0xffffffffu, e1, 1);
                float f2 = __shfl_down_sync(0xffffffffu, e2, 1);
                float f3 = __shfl_down_sync(0xffffffffu, e3, 1);
                bool last = (nh == 1 && jj == 11);   // cols 192-199: only 192-195 valid
                if ((g & 1) == 0 && (!last || g == 0)) {
                    if (ok0) red4(P0 + colb, e0, e1, f0, f1);
                    if (ok1) red4(P1 + colb, e2, e3, f2, f3);
                }
            }
        }
    }
}

// ---------------------------------------------------------------------------
// Kernel 2 — EXACT ROUND-13 VERSION (protected): fused halves, np-merged,
// c-tile-paired, cp.async double-buffered gather.
// ---------------------------------------------------------------------------
#define TCo 64
#define WSF (98 * TCo)                  // 6272 floats per ws buffer
#define PSF (4 * LL * 8)                // 6272 floats per half
#define RED_U64 (4 * 32 * 8)            // 1024 u64 = 8192 B
#define O_SMEM_BYTES ((2*WSF + 2*PSF) * 4 + RED_U64 * 8)   // 108544 B

__global__ __launch_bounds__(256, 2)
void out_kernel(const float* __restrict__ w1, const float* __restrict__ w2,
                float* __restrict__ out) {
    extern __shared__ float sm[];
    float* psA = sm + 2 * WSF;
    float* psB = psA + PSF;
    u64*   red = (u64*)(sm + 2 * WSF + 2 * PSF);

    int qq = blockIdx.y;
    int c0 = blockIdx.x * (2 * TCo);
    int tid = threadIdx.x;
    int pi = qq / 14, pj = qq - pi * 14;

    uint32_t ws_s0 = (uint32_t)__cvta_generic_to_shared(sm);

    #pragma unroll
    for (int r = 0; r < 28; r++) {
        int n_l = r / 7, t = r - n_l * 7;
        if (tid < LL) {
            size_t base = ((size_t)(n_l * 7 + t) * LL + qq) * LL + tid;
            psA[n_l * (LL * 8) + tid * 8 + t + 1] = g_P1[base];
            psB[n_l * (LL * 8) + tid * 8 + t]     = g_P2[base];
        }
    }
    if (tid < LL) {
        #pragma unroll
        for (int n_l = 0; n_l < 4; n_l++) {
            psA[n_l * (LL * 8) + tid * 8] = 0.f;
            psB[n_l * (LL * 8) + tid * 8 + 7] = 0.f;
        }
    }

    int wid = tid >> 5, lane = tid & 31;
    int n_l = wid >> 1, kq = wid & 1;
    int sub = lane >> 4, cl = lane & 15;
    int kst = kq * 49;

    auto gather = [&](int pp) {
        int ch = pp >> 2, ph = pp & 3;
        const float* w = (ph < 2) ? w1 : w2;
        int kbase = (ph & 1) * 98;
        int cc = c0 + ch * TCo;
        uint32_t dst = ws_s0 + (uint32_t)(pp & 1) * (WSF * 4);
        #pragma unroll
        for (int j = 0; j < 6; j++) {
            int i = tid + j * 256;
            int kk = i >> 4, cq = i & 15;
            int kg = kbase + kk;
            int ki = kg / 14, kj = kg - ki * 14;
            int idx = (pi - ki + 13) * 27 + (pj - kj + 13);
            cpa16(dst + (uint32_t)(kk * TCo + cq * 4) * 4,
                  w + (size_t)idx * CC + cc + cq * 4);
        }
        if (tid < 32) {
            int i = 1536 + tid;
            int kk = i >> 4, cq = i & 15;
            int kg = kbase + kk;
            int ki = kg / 14, kj = kg - ki * 14;
            int idx = (pi - ki + 13) * 27 + (pj - kj + 13);
            cpa16(dst + (uint32_t)(kk * TCo + cq * 4) * 4,
                  w + (size_t)idx * CC + cc + cq * 4);
        }
        CPA_COMMIT();
    };

    u64 acc[8];
    #pragma unroll
    for (int i = 0; i < 8; i++) acc[i] = 0ULL;

    gather(0);
    for (int pp = 0; pp < 8; pp++) {
        if (pp < 7) { gather(pp + 1); CPA_WAIT(1); }
        else        { CPA_WAIT(0); }
        __syncthreads();

        int ph = pp & 3, ch = pp >> 2;
        const float* ps = ((ph < 2) ? psA : psB) + n_l * (LL * 8);
        int kbase = (ph & 1) * 98;
        const float* ws = sm + (pp & 1) * WSF;

        #pragma unroll 7
        for (int kl = kst; kl < kst + 49; kl++) {
            float4 wv = *(const float4*)&ws[kl * TCo + cl * 4];
            ulonglong2 pr = *(const ulonglong2*)&ps[(kbase + kl) * 8 + sub * 4];
            u64 b0 = pk2(wv.x, wv.x), b1 = pk2(wv.y, wv.y);
            u64 b2 = pk2(wv.z, wv.z), b3 = pk2(wv.w, wv.w);
            acc[0] = ffma2(pr.x, b0, acc[0]);  acc[1] = ffma2(pr.y, b0, acc[1]);
            acc[2] = ffma2(pr.x, b1, acc[2]);  acc[3] = ffma2(pr.y, b1, acc[3]);
            acc[4] = ffma2(pr.x, b2, acc[4]);  acc[5] = ffma2(pr.y, b2, acc[5]);
            acc[6] = ffma2(pr.x, b3, acc[6]);  acc[7] = ffma2(pr.y, b3, acc[7]);
        }

        bool epi = ((pp & 3) == 3);
        if (epi && kq) {
            int base = (n_l * 32 + lane) * 8;
            #pragma unroll
            for (int j = 0; j < 8; j++) red[base + j] = acc[j];
        }
        __syncthreads();

        if (epi) {
            if (kq == 0) {
                int base = (n_l * 32 + lane) * 8;
                #pragma unroll
                for (int j = 0; j < 8; j++) acc[j] = fadd2(acc[j], red[base + j]);

                int cc = c0 + ch * TCo;
                float a[16];
                #pragma unroll
                for (int i = 0; i < 8; i++) upk2(acc[i], a[2 * i], a[2 * i + 1]);
                #pragma unroll
                for (int tl = 0; tl < 4; tl++) {
                    int tt = sub * 4 + tl;
                    int tp = tl >> 1, hi = tl & 1;
                    float4 o4;
                    o4.x = a[(0 * 2 + tp) * 2 + hi];
                    o4.y = a[(1 * 2 + tp) * 2 + hi];
                    o4.z = a[(2 * 2 + tp) * 2 + hi];
                    o4.w = a[(3 * 2 + tp) * 2 + hi];
                    *(float4*)(out + ((size_t)(n_l * TDIM + tt) * LP1 + qq + 1) * CC
                               + cc + cl * 4) = o4;
                }
            }
            #pragma unroll
            for (int i = 0; i < 8; i++) acc[i] = 0ULL;
        }
    }
}

// ---------------------------------------------------------------------------
extern "C" void kernel_launch(void* const* d_in, const int* in_sizes, int n_in,
                              void* d_out, int out_size) {
    const float* q  = (const float*)d_in[0];
    const float* k  = (const float*)d_in[1];
    const float* w1 = (const float*)d_in[2];
    const float* w2 = (const float*)d_in[3];
    float* out = (float*)d_out;

    cudaFuncSetAttribute(attn_kernel, cudaFuncAttributeMaxDynamicSharedMemorySize, A_SMEM_BYTES);
    cudaFuncSetAttribute(out_kernel,  cudaFuncAttributeMaxDynamicSharedMemorySize, O_SMEM_BYTES);

    zero_kernel<<<512, 256>>>(out);
    attn_kernel<<<dim3(HH, NT, 6), 256, A_SMEM_BYTES>>>(q, k);
    out_kernel<<<dim3(CC / (2 * TCo), LL, 1), 256, O_SMEM_BYTES>>>(w1, w2, out);
}